// round 13
// baseline (speedup 1.0000x reference)
#include <cuda_runtime.h>
#include <cuda_bf16.h>
#include <stdint.h>
#include <math.h>

#define BATCH   4096
#define LATENT  2048
#define ZDIM    128
#define NROWS   8192
#define TDIM    128
#define NTILES  64
#define NPAIRS  2080          // 64*65/2 upper-triangular tiles
#define TEMP_INV 2.0f
#define PRIOR        0.3f
#define PRIOR_PRIME  0.5f

#define PU_BLOCKS   256       // 32 rows each (128 blocks h_i, 128 h_j)
#define NORM_BLOCKS 1024      // 8 warps -> 8 rows each

// ---------------- scratch (zero-init at load; sim tail restores zeros) -------
__device__ __nv_bfloat16 g_zb[NROWS * ZDIM];  // normalized z, bf16
__device__ float    g_S[NROWS];               // per-row sum exp(sim), diag excl
__device__ float    g_acc[8];                 // 0..2 h_i PU, 3..5 h_j, 6 pos
__device__ unsigned g_ctr = 0;                // sim-block arrival counter

// ---------------- helpers ------------------------------------------------------
__device__ __forceinline__ void ldmx4(uint32_t& r0, uint32_t& r1,
                                      uint32_t& r2, uint32_t& r3, uint32_t addr) {
    asm volatile("ldmatrix.sync.aligned.m8n8.x4.shared.b16 {%0,%1,%2,%3}, [%4];"
                 : "=r"(r0), "=r"(r1), "=r"(r2), "=r"(r3) : "r"(addr));
}
__device__ __forceinline__ void mma16816(float* d, const uint32_t* a,
                                         uint32_t b0, uint32_t b1) {
    asm volatile("mma.sync.aligned.m16n8k16.row.col.f32.bf16.bf16.f32 "
                 "{%0,%1,%2,%3}, {%4,%5,%6,%7}, {%8,%9}, {%0,%1,%2,%3};"
                 : "+f"(d[0]), "+f"(d[1]), "+f"(d[2]), "+f"(d[3])
                 : "r"(a[0]), "r"(a[1]), "r"(a[2]), "r"(a[3]), "r"(b0), "r"(b1));
}
__device__ __forceinline__ void cp16(uint32_t smem_dst, const void* gmem_src) {
    asm volatile("cp.async.cg.shared.global [%0], [%1], 16;"
                 :: "r"(smem_dst), "l"(gmem_src));
}

// ---------------- prep: PU logits (LDG streaming) + z normalize ---------------
// grid = 1280 x 256: blocks 0..255 PU (32 rows each), 256..1279 norm (8 rows).
__global__ __launch_bounds__(256)
void prep_kernel(const float* __restrict__ h_i,
                 const float* __restrict__ h_j,
                 const float* __restrict__ z_i,
                 const float* __restrict__ z_j,
                 const float* __restrict__ W,
                 const float* __restrict__ b,
                 const int*   __restrict__ target) {
    int bid  = blockIdx.x;
    int tid  = threadIdx.x;
    int wid  = tid >> 5;
    int lane = tid & 31;

    if (bid < PU_BLOCKS) {
        __shared__ float rowAcc[32];
        bool is_i = (bid < 128);
        int r0 = (is_i ? bid : bid - 128) * 32;
        const float* hbase = (is_i ? h_i : h_j) + (size_t)r0 * LATENT;

        // W half-row -> registers (reused across 8 rows)
        int half = wid & 1;
        const float4* wv = (const float4*)W;
        float4 wreg[8];
#pragma unroll
        for (int k = 0; k < 8; ++k) wreg[k] = wv[half * 256 + lane + k * 32];

        if (tid < 32) rowAcc[tid] = 0.0f;
        __syncthreads();

        // warp pair (wid>>1) handles rows [pair*8, pair*8+8), split by half
        int rbase = (wid >> 1) * 8;
#pragma unroll 2
        for (int rr = 0; rr < 8; ++rr) {
            int row = rbase + rr;
            const float4* hrow = (const float4*)(hbase + (size_t)row * LATENT);
            float a0 = 0.0f, a1 = 0.0f, a2 = 0.0f, a3 = 0.0f;
#pragma unroll
            for (int k = 0; k < 8; ++k) {
                float4 a = hrow[half * 256 + lane + k * 32];
                float4 w = wreg[k];
                if ((k & 3) == 0) a0 += a.x * w.x + a.y * w.y + a.z * w.z + a.w * w.w;
                else if ((k & 3) == 1) a1 += a.x * w.x + a.y * w.y + a.z * w.z + a.w * w.w;
                else if ((k & 3) == 2) a2 += a.x * w.x + a.y * w.y + a.z * w.z + a.w * w.w;
                else a3 += a.x * w.x + a.y * w.y + a.z * w.z + a.w * w.w;
            }
            float acc = (a0 + a1) + (a2 + a3);
#pragma unroll
            for (int m = 16; m; m >>= 1) acc += __shfl_xor_sync(0xffffffffu, acc, m);
            if (lane == 0) atomicAdd(&rowAcc[row], acc);
        }
        __syncthreads();

        if (tid < 32) {
            float logit = rowAcc[tid] + b[0];
            int t = target[r0 + tid];
            float sig_neg = 1.0f / (1.0f + __expf(logit));
            float sig_pos = 1.0f / (1.0f + __expf(-logit));
            float ypos    = (t == 1) ? sig_neg : 0.0f;
            float yposinv = (t == 1) ? sig_pos : 0.0f;
            float yunl    = (t == 1) ? 0.0f : sig_pos;
#pragma unroll
            for (int m = 16; m; m >>= 1) {
                ypos    += __shfl_xor_sync(0xffffffffu, ypos, m);
                yposinv += __shfl_xor_sync(0xffffffffu, yposinv, m);
                yunl    += __shfl_xor_sync(0xffffffffu, yunl, m);
            }
            if (lane == 0) {
                int base = is_i ? 0 : 3;
                atomicAdd(&g_acc[base + 0], ypos);
                atomicAdd(&g_acc[base + 1], yposinv);
                atomicAdd(&g_acc[base + 2], yunl);
            }
        }
    } else {
        // norm role: one warp per z row
        int gw = (bid - PU_BLOCKS) * 8 + wid;    // 0..8191
        const float* z = (gw < BATCH) ? (z_i + (size_t)gw * ZDIM)
                                      : (z_j + (size_t)(gw - BATCH) * ZDIM);
        float4 v = ((const float4*)z)[lane];
        float ss = v.x * v.x + v.y * v.y + v.z * v.z + v.w * v.w;
#pragma unroll
        for (int m = 16; m; m >>= 1) ss += __shfl_xor_sync(0xffffffffu, ss, m);
        float scale = 1.0f / fmaxf(sqrtf(ss), 1e-8f);
        __nv_bfloat162 p0 = __floats2bfloat162_rn(v.x * scale, v.y * scale);
        __nv_bfloat162 p1 = __floats2bfloat162_rn(v.z * scale, v.w * scale);
        __nv_bfloat162* o = (__nv_bfloat162*)(g_zb + (size_t)gw * ZDIM);
        o[lane * 2]     = p0;
        o[lane * 2 + 1] = p1;
    }
}

// ---------------- similarity kernel + fused finalize --------------------------
// R7 core: 1 tile/CTA, 128 threads = 4 warps in 2x2, 64x64 warp tiles.
// Last block (atomic ticket) computes the loss and resets scratch state.
__global__ __launch_bounds__(128)
void sim_kernel(const int*   __restrict__ target,
                const float* __restrict__ w_onnpu,
                float*       __restrict__ out) {
    extern __shared__ unsigned char smem[];
    __nv_bfloat16* As = (__nv_bfloat16*)smem;            // 32 KB
    __nv_bfloat16* Bs = (__nv_bfloat16*)(smem + 32768);  // 32 KB
    float* rowS = (float*)(smem + 65536);                // 128
    float* colS = rowS + 128;                            // 128
    float* posS = colS + 128;                            // 1

    int tid  = threadIdx.x;
    int lane = tid & 31, wid = tid >> 5;
    int wm = wid >> 1, wn = wid & 1;

    int t = blockIdx.x;
    int bi = 0, rem = t;
    while (rem >= NTILES - bi) { rem -= NTILES - bi; ++bi; }
    int bj = bi + rem;
    int rowbase = bi * TDIM, colbase = bj * TDIM;
    bool diag    = (bi == bj);
    bool has_pos = (bj == bi + 32);

    rowS[tid] = 0.0f;
    colS[tid] = 0.0f;
    if (tid == 0) posS[0] = 0.0f;

    const uint4* Z = (const uint4*)g_zb;
    uint32_t Abase = (uint32_t)__cvta_generic_to_shared(As);
    uint32_t Bbase = (uint32_t)__cvta_generic_to_shared(Bs);
#pragma unroll
    for (int l = 0; l < 16; ++l) {
        int idx = tid + l * 128;
        int r = idx >> 4, c = idx & 15;
        int cs = c ^ (r & 7);
        cp16(Abase + (r * 16 + cs) * 16, Z + (rowbase + r) * 16 + c);
        cp16(Bbase + (r * 16 + cs) * 16, Z + (colbase + r) * 16 + c);
    }
    asm volatile("cp.async.commit_group;" ::: "memory");
    asm volatile("cp.async.wait_group 0;" ::: "memory");
    __syncthreads();

    int lr = (lane & 7) + ((lane >> 3) & 1) * 8;
    int lh = lane >> 4;
    int key = lane & 7;

    int rowA[4], rowB[4];
#pragma unroll
    for (int am = 0; am < 4; ++am) rowA[am] = (wm * 64 + am * 16 + lr) * 16;
#pragma unroll
    for (int p = 0; p < 4; ++p)    rowB[p] = (wn * 64 + p * 16 + lr) * 16;

    float acc[4][8][4];
#pragma unroll
    for (int am = 0; am < 4; ++am)
#pragma unroll
        for (int an = 0; an < 8; ++an)
#pragma unroll
            for (int k = 0; k < 4; ++k) acc[am][an][k] = 0.0f;

#pragma unroll
    for (int ks = 0; ks < 8; ++ks) {
        int c = (2 * ks + lh) ^ key;
        uint32_t a[4][4];
        uint32_t bq[4][4];
#pragma unroll
        for (int am = 0; am < 4; ++am)
            ldmx4(a[am][0], a[am][1], a[am][2], a[am][3],
                  Abase + ((rowA[am] + c) << 4));
#pragma unroll
        for (int p = 0; p < 4; ++p)
            ldmx4(bq[p][0], bq[p][1], bq[p][2], bq[p][3],
                  Bbase + ((rowB[p] + c) << 4));
#pragma unroll
        for (int am = 0; am < 4; ++am) {
#pragma unroll
            for (int p = 0; p < 4; ++p) {
                mma16816(acc[am][2 * p],     a[am], bq[p][0], bq[p][2]);
                mma16816(acc[am][2 * p + 1], a[am], bq[p][1], bq[p][3]);
            }
        }
    }

    int qr = lane >> 2, qc = lane & 3;
    float rs[8], cs[16];
#pragma unroll
    for (int i = 0; i < 8; ++i)  rs[i] = 0.0f;
#pragma unroll
    for (int i = 0; i < 16; ++i) cs[i] = 0.0f;
    float pos = 0.0f;

#pragma unroll
    for (int am = 0; am < 4; ++am) {
        int r0l = wm * 64 + am * 16 + qr;
#pragma unroll
        for (int an = 0; an < 8; ++an) {
            int c0l = wn * 64 + an * 8 + 2 * qc;
#pragma unroll
            for (int k = 0; k < 4; ++k) {
                int rl = r0l + (k >> 1) * 8;
                int cl = c0l + (k & 1);
                float v = acc[am][an][k] * TEMP_INV;
                float e = __expf(v);
                if (diag && rl == cl) e = 0.0f;
                rs[am * 2 + (k >> 1)] += e;
                cs[an * 2 + (k & 1)]  += e;
                if (has_pos && rl == cl) pos += v;
            }
        }
    }

#pragma unroll
    for (int i = 0; i < 8; ++i) {
        rs[i] += __shfl_xor_sync(0xffffffffu, rs[i], 1);
        rs[i] += __shfl_xor_sync(0xffffffffu, rs[i], 2);
    }
    if (qc == 0) {
#pragma unroll
        for (int i = 0; i < 8; ++i)
            atomicAdd(&rowS[wm * 64 + (i >> 1) * 16 + qr + (i & 1) * 8], rs[i]);
    }
#pragma unroll
    for (int i = 0; i < 16; ++i) {
        cs[i] += __shfl_xor_sync(0xffffffffu, cs[i], 4);
        cs[i] += __shfl_xor_sync(0xffffffffu, cs[i], 8);
        cs[i] += __shfl_xor_sync(0xffffffffu, cs[i], 16);
    }
    if (lane < 4) {
#pragma unroll
        for (int i = 0; i < 16; ++i)
            atomicAdd(&colS[wn * 64 + (i >> 1) * 8 + 2 * lane + (i & 1)], cs[i]);
    }
    if (has_pos) {
#pragma unroll
        for (int m = 16; m; m >>= 1) pos += __shfl_xor_sync(0xffffffffu, pos, m);
        if (lane == 0) atomicAdd(posS, pos);
    }
    __syncthreads();

    atomicAdd(&g_S[rowbase + tid], rowS[tid]);
    if (!diag) atomicAdd(&g_S[colbase + tid], colS[tid]);
    if (has_pos && tid == 0) atomicAdd(&g_acc[6], posS[0] * 2.0f);

    // ---------------- fused finalize (last block) -----------------------------
    __threadfence();          // every thread: its global atomics -> visible
    __syncthreads();
    __shared__ int lastflag;
    if (tid == 0) {
        unsigned old = atomicInc(&g_ctr, NPAIRS - 1);   // wraps to 0 on last
        lastflag = (old == NPAIRS - 1);
    }
    __syncthreads();
    if (!lastflag) return;
    __threadfence();          // acquire: see all blocks' g_S / g_acc

    float* redf = rowS;       // reuse smem scratch
    int*   redi = (int*)colS;
    float l = 0.0f;
    for (int i = tid; i < NROWS; i += 128) l += __logf(g_S[i]);
    int np = 0;
    for (int i = tid; i < BATCH; i += 128) np += (target[i] == 1);
#pragma unroll
    for (int m = 16; m; m >>= 1) {
        l  += __shfl_xor_sync(0xffffffffu, l, m);
        np += __shfl_xor_sync(0xffffffffu, np, m);
    }
    if (lane == 0) { redf[wid] = l; redi[wid] = np; }
    __syncthreads();
    if (tid == 0) {
        float logsum = redf[0] + redf[1] + redf[2] + redf[3];
        int   npos   = redi[0] + redi[1] + redi[2] + redi[3];
        float n_pos = fmaxf(1.0f, (float)npos);
        float n_unl = fmaxf(1.0f, (float)(BATCH - npos));
        float nt = (logsum - g_acc[6]) / (float)NROWS;
        float li, lj;
        {
            float prisk = PRIOR_PRIME / n_pos * g_acc[0];
            float nrisk = (1.0f - PRIOR_PRIME) / (n_unl * (1.0f - PRIOR)) * g_acc[2]
                        - (1.0f - PRIOR_PRIME) * PRIOR / (n_pos * (1.0f - PRIOR)) * g_acc[1];
            li = (nrisk < 0.0f) ? -nrisk : (prisk + nrisk);
        }
        {
            float prisk = PRIOR_PRIME / n_pos * g_acc[3];
            float nrisk = (1.0f - PRIOR_PRIME) / (n_unl * (1.0f - PRIOR)) * g_acc[5]
                        - (1.0f - PRIOR_PRIME) * PRIOR / (n_pos * (1.0f - PRIOR)) * g_acc[4];
            lj = (nrisk < 0.0f) ? -nrisk : (prisk + nrisk);
        }
        float w = w_onnpu[0];
        out[0] = w * 0.5f * (li + lj) + (1.0f - w) * nt;
        // reset scalars for next graph replay (g_ctr already wrapped)
#pragma unroll
        for (int k = 0; k < 8; ++k) g_acc[k] = 0.0f;
    }
    // reset g_S cooperatively
    for (int k = tid; k < NROWS; k += 128) g_S[k] = 0.0f;
}

// ---------------- launch ------------------------------------------------------
extern "C" void kernel_launch(void* const* d_in, const int* in_sizes, int n_in,
                              void* d_out, int out_size) {
    const float* h_i = (const float*)d_in[0];
    const float* h_j = (const float*)d_in[1];
    const float* z_i = (const float*)d_in[2];
    const float* z_j = (const float*)d_in[3];
    const int*   tgt = (const int*)  d_in[4];
    const float* W   = (const float*)d_in[5];
    const float* b   = (const float*)d_in[6];
    const float* wgt = (const float*)d_in[7];
    float* out = (float*)d_out;

    static int smem_set = 0;
    const int SIM_SMEM = 65536 + (128 + 128 + 1) * (int)sizeof(float);  // 66564
    if (!smem_set) {
        cudaFuncSetAttribute(sim_kernel,
                             cudaFuncAttributeMaxDynamicSharedMemorySize, SIM_SMEM);
        smem_set = 1;
    }

    prep_kernel<<<PU_BLOCKS + NORM_BLOCKS, 256>>>(h_i, h_j, z_i, z_j, W, b, tgt);
    sim_kernel<<<NPAIRS, 128, SIM_SMEM>>>(tgt, wgt, out);
}

// round 14
// speedup vs baseline: 1.2384x; 1.2384x over previous
#include <cuda_runtime.h>
#include <cuda_bf16.h>
#include <stdint.h>
#include <math.h>

#define BATCH   4096
#define LATENT  2048
#define ZDIM    128
#define NROWS   8192
#define TDIM    128
#define NTILES  64
#define NPAIRS  2080          // 64*65/2 upper-triangular tiles
#define TEMP_INV 2.0f
#define PRIOR        0.3f
#define PRIOR_PRIME  0.5f

#define PU_BLOCKS   256       // 32 rows each (128 blocks h_i, 128 h_j)
#define NORM_BLOCKS 1024      // 8 warps -> 8 rows each

// ---------------- scratch (zero-init at load; final_kernel restores zeros) ---
__device__ __nv_bfloat16 g_zb[NROWS * ZDIM];  // normalized z, bf16
__device__ float    g_S[NROWS];               // per-row sum exp(sim), diag excl
__device__ float    g_acc[8];                 // 0..2 h_i PU, 3..5 h_j, 6 pos, 7 logsum
__device__ int      g_np = 0;                 // positive count
__device__ unsigned g_ctr = 0;                // final arrival counter

// ---------------- helpers ------------------------------------------------------
__device__ __forceinline__ void ldmx4(uint32_t& r0, uint32_t& r1,
                                      uint32_t& r2, uint32_t& r3, uint32_t addr) {
    asm volatile("ldmatrix.sync.aligned.m8n8.x4.shared.b16 {%0,%1,%2,%3}, [%4];"
                 : "=r"(r0), "=r"(r1), "=r"(r2), "=r"(r3) : "r"(addr));
}
__device__ __forceinline__ void mma16816(float* d, const uint32_t* a,
                                         uint32_t b0, uint32_t b1) {
    asm volatile("mma.sync.aligned.m16n8k16.row.col.f32.bf16.bf16.f32 "
                 "{%0,%1,%2,%3}, {%4,%5,%6,%7}, {%8,%9}, {%0,%1,%2,%3};"
                 : "+f"(d[0]), "+f"(d[1]), "+f"(d[2]), "+f"(d[3])
                 : "r"(a[0]), "r"(a[1]), "r"(a[2]), "r"(a[3]), "r"(b0), "r"(b1));
}
__device__ __forceinline__ void cp16(uint32_t smem_dst, const void* gmem_src) {
    asm volatile("cp.async.cg.shared.global [%0], [%1], 16;"
                 :: "r"(smem_dst), "l"(gmem_src));
}

// ---------------- prep: PU logits (LDG streaming) + z normalize ---------------
// grid = 1280 x 256: blocks 0..255 PU (32 rows each), 256..1279 norm (8 rows).
__global__ __launch_bounds__(256)
void prep_kernel(const float* __restrict__ h_i,
                 const float* __restrict__ h_j,
                 const float* __restrict__ z_i,
                 const float* __restrict__ z_j,
                 const float* __restrict__ W,
                 const float* __restrict__ b,
                 const int*   __restrict__ target) {
    int bid  = blockIdx.x;
    int tid  = threadIdx.x;
    int wid  = tid >> 5;
    int lane = tid & 31;

    if (bid < PU_BLOCKS) {
        __shared__ float rowAcc[32];
        bool is_i = (bid < 128);
        int r0 = (is_i ? bid : bid - 128) * 32;
        const float* hbase = (is_i ? h_i : h_j) + (size_t)r0 * LATENT;

        // W half-row -> registers (reused across 8 rows)
        int half = wid & 1;
        const float4* wv = (const float4*)W;
        float4 wreg[8];
#pragma unroll
        for (int k = 0; k < 8; ++k) wreg[k] = wv[half * 256 + lane + k * 32];

        if (tid < 32) rowAcc[tid] = 0.0f;
        __syncthreads();

        // warp pair (wid>>1) handles rows [pair*8, pair*8+8), split by half
        int rbase = (wid >> 1) * 8;
#pragma unroll 2
        for (int rr = 0; rr < 8; ++rr) {
            int row = rbase + rr;
            const float4* hrow = (const float4*)(hbase + (size_t)row * LATENT);
            float a0 = 0.0f, a1 = 0.0f, a2 = 0.0f, a3 = 0.0f;
#pragma unroll
            for (int k = 0; k < 8; ++k) {
                float4 a = hrow[half * 256 + lane + k * 32];
                float4 w = wreg[k];
                if ((k & 3) == 0) a0 += a.x * w.x + a.y * w.y + a.z * w.z + a.w * w.w;
                else if ((k & 3) == 1) a1 += a.x * w.x + a.y * w.y + a.z * w.z + a.w * w.w;
                else if ((k & 3) == 2) a2 += a.x * w.x + a.y * w.y + a.z * w.z + a.w * w.w;
                else a3 += a.x * w.x + a.y * w.y + a.z * w.z + a.w * w.w;
            }
            float acc = (a0 + a1) + (a2 + a3);
#pragma unroll
            for (int m = 16; m; m >>= 1) acc += __shfl_xor_sync(0xffffffffu, acc, m);
            if (lane == 0) atomicAdd(&rowAcc[row], acc);
        }
        __syncthreads();

        if (tid < 32) {
            float logit = rowAcc[tid] + b[0];
            int t = target[r0 + tid];
            float sig_neg = 1.0f / (1.0f + __expf(logit));
            float sig_pos = 1.0f / (1.0f + __expf(-logit));
            float ypos    = (t == 1) ? sig_neg : 0.0f;
            float yposinv = (t == 1) ? sig_pos : 0.0f;
            float yunl    = (t == 1) ? 0.0f : sig_pos;
#pragma unroll
            for (int m = 16; m; m >>= 1) {
                ypos    += __shfl_xor_sync(0xffffffffu, ypos, m);
                yposinv += __shfl_xor_sync(0xffffffffu, yposinv, m);
                yunl    += __shfl_xor_sync(0xffffffffu, yunl, m);
            }
            if (lane == 0) {
                int base = is_i ? 0 : 3;
                atomicAdd(&g_acc[base + 0], ypos);
                atomicAdd(&g_acc[base + 1], yposinv);
                atomicAdd(&g_acc[base + 2], yunl);
            }
        }
    } else {
        // norm role: one warp per z row
        int gw = (bid - PU_BLOCKS) * 8 + wid;    // 0..8191
        const float* z = (gw < BATCH) ? (z_i + (size_t)gw * ZDIM)
                                      : (z_j + (size_t)(gw - BATCH) * ZDIM);
        float4 v = ((const float4*)z)[lane];
        float ss = v.x * v.x + v.y * v.y + v.z * v.z + v.w * v.w;
#pragma unroll
        for (int m = 16; m; m >>= 1) ss += __shfl_xor_sync(0xffffffffu, ss, m);
        float scale = 1.0f / fmaxf(sqrtf(ss), 1e-8f);
        __nv_bfloat162 p0 = __floats2bfloat162_rn(v.x * scale, v.y * scale);
        __nv_bfloat162 p1 = __floats2bfloat162_rn(v.z * scale, v.w * scale);
        __nv_bfloat162* o = (__nv_bfloat162*)(g_zb + (size_t)gw * ZDIM);
        o[lane * 2]     = p0;
        o[lane * 2 + 1] = p1;
    }
}

// ---------------- similarity kernel (bf16 HMMA, 64x64 warp tiles) -------------
// EXACT R7 form (proven ~28us): 1 tile/CTA, 128 threads = 4 warps in 2x2.
__global__ __launch_bounds__(128)
void sim_kernel() {
    extern __shared__ unsigned char smem[];
    __nv_bfloat16* As = (__nv_bfloat16*)smem;            // 32 KB
    __nv_bfloat16* Bs = (__nv_bfloat16*)(smem + 32768);  // 32 KB
    float* rowS = (float*)(smem + 65536);                // 128
    float* colS = rowS + 128;                            // 128
    float* posS = colS + 128;                            // 1

    int tid  = threadIdx.x;
    int lane = tid & 31, wid = tid >> 5;
    int wm = wid >> 1, wn = wid & 1;

    int t = blockIdx.x;
    int bi = 0, rem = t;
    while (rem >= NTILES - bi) { rem -= NTILES - bi; ++bi; }
    int bj = bi + rem;
    int rowbase = bi * TDIM, colbase = bj * TDIM;
    bool diag    = (bi == bj);
    bool has_pos = (bj == bi + 32);

    rowS[tid] = 0.0f;
    colS[tid] = 0.0f;
    if (tid == 0) posS[0] = 0.0f;

    const uint4* Z = (const uint4*)g_zb;
    uint32_t Abase = (uint32_t)__cvta_generic_to_shared(As);
    uint32_t Bbase = (uint32_t)__cvta_generic_to_shared(Bs);
#pragma unroll
    for (int l = 0; l < 16; ++l) {
        int idx = tid + l * 128;
        int r = idx >> 4, c = idx & 15;
        int cs = c ^ (r & 7);
        cp16(Abase + (r * 16 + cs) * 16, Z + (rowbase + r) * 16 + c);
        cp16(Bbase + (r * 16 + cs) * 16, Z + (colbase + r) * 16 + c);
    }
    asm volatile("cp.async.commit_group;" ::: "memory");
    asm volatile("cp.async.wait_group 0;" ::: "memory");
    __syncthreads();

    int lr = (lane & 7) + ((lane >> 3) & 1) * 8;
    int lh = lane >> 4;
    int key = lane & 7;

    int rowA[4], rowB[4];
#pragma unroll
    for (int am = 0; am < 4; ++am) rowA[am] = (wm * 64 + am * 16 + lr) * 16;
#pragma unroll
    for (int p = 0; p < 4; ++p)    rowB[p] = (wn * 64 + p * 16 + lr) * 16;

    float acc[4][8][4];
#pragma unroll
    for (int am = 0; am < 4; ++am)
#pragma unroll
        for (int an = 0; an < 8; ++an)
#pragma unroll
            for (int k = 0; k < 4; ++k) acc[am][an][k] = 0.0f;

#pragma unroll
    for (int ks = 0; ks < 8; ++ks) {
        int c = (2 * ks + lh) ^ key;
        uint32_t a[4][4];
        uint32_t bq[4][4];
#pragma unroll
        for (int am = 0; am < 4; ++am)
            ldmx4(a[am][0], a[am][1], a[am][2], a[am][3],
                  Abase + ((rowA[am] + c) << 4));
#pragma unroll
        for (int p = 0; p < 4; ++p)
            ldmx4(bq[p][0], bq[p][1], bq[p][2], bq[p][3],
                  Bbase + ((rowB[p] + c) << 4));
#pragma unroll
        for (int am = 0; am < 4; ++am) {
#pragma unroll
            for (int p = 0; p < 4; ++p) {
                mma16816(acc[am][2 * p],     a[am], bq[p][0], bq[p][2]);
                mma16816(acc[am][2 * p + 1], a[am], bq[p][1], bq[p][3]);
            }
        }
    }

    int qr = lane >> 2, qc = lane & 3;
    float rs[8], cs[16];
#pragma unroll
    for (int i = 0; i < 8; ++i)  rs[i] = 0.0f;
#pragma unroll
    for (int i = 0; i < 16; ++i) cs[i] = 0.0f;
    float pos = 0.0f;

#pragma unroll
    for (int am = 0; am < 4; ++am) {
        int r0l = wm * 64 + am * 16 + qr;
#pragma unroll
        for (int an = 0; an < 8; ++an) {
            int c0l = wn * 64 + an * 8 + 2 * qc;
#pragma unroll
            for (int k = 0; k < 4; ++k) {
                int rl = r0l + (k >> 1) * 8;
                int cl = c0l + (k & 1);
                float v = acc[am][an][k] * TEMP_INV;
                float e = __expf(v);
                if (diag && rl == cl) e = 0.0f;
                rs[am * 2 + (k >> 1)] += e;
                cs[an * 2 + (k & 1)]  += e;
                if (has_pos && rl == cl) pos += v;
            }
        }
    }

#pragma unroll
    for (int i = 0; i < 8; ++i) {
        rs[i] += __shfl_xor_sync(0xffffffffu, rs[i], 1);
        rs[i] += __shfl_xor_sync(0xffffffffu, rs[i], 2);
    }
    if (qc == 0) {
#pragma unroll
        for (int i = 0; i < 8; ++i)
            atomicAdd(&rowS[wm * 64 + (i >> 1) * 16 + qr + (i & 1) * 8], rs[i]);
    }
#pragma unroll
    for (int i = 0; i < 16; ++i) {
        cs[i] += __shfl_xor_sync(0xffffffffu, cs[i], 4);
        cs[i] += __shfl_xor_sync(0xffffffffu, cs[i], 8);
        cs[i] += __shfl_xor_sync(0xffffffffu, cs[i], 16);
    }
    if (lane < 4) {
#pragma unroll
        for (int i = 0; i < 16; ++i)
            atomicAdd(&colS[wn * 64 + (i >> 1) * 8 + 2 * lane + (i & 1)], cs[i]);
    }
    if (has_pos) {
#pragma unroll
        for (int m = 16; m; m >>= 1) pos += __shfl_xor_sync(0xffffffffu, pos, m);
        if (lane == 0) atomicAdd(posS, pos);
    }
    __syncthreads();

    atomicAdd(&g_S[rowbase + tid], rowS[tid]);
    if (!diag) atomicAdd(&g_S[colbase + tid], colS[tid]);
    if (has_pos && tid == 0) atomicAdd(&g_acc[6], posS[0] * 2.0f);
}

// ---------------- finalize (parallel, single launch, self-resetting) ----------
__global__ void final_kernel(const int* __restrict__ target,
                             const float* __restrict__ w_onnpu,
                             float* __restrict__ out) {
    __shared__ float wsf[4];
    __shared__ int   wsi[4];
    __shared__ int   lastflag;
    int tid  = threadIdx.x;
    int lane = tid & 31, wid = tid >> 5;
    int i = blockIdx.x * 128 + tid;

    float l = __logf(g_S[i]);
    int np = (i < BATCH) ? (target[i] == 1) : 0;
#pragma unroll
    for (int m = 16; m; m >>= 1) {
        l  += __shfl_xor_sync(0xffffffffu, l, m);
        np += __shfl_xor_sync(0xffffffffu, np, m);
    }
    if (lane == 0) { wsf[wid] = l; wsi[wid] = np; }
    __syncthreads();
    if (tid == 0) {
        float bs = wsf[0] + wsf[1] + wsf[2] + wsf[3];
        int   bn = wsi[0] + wsi[1] + wsi[2] + wsi[3];
        atomicAdd(&g_acc[7], bs);
        if (bn) atomicAdd(&g_np, bn);
        __threadfence();
        unsigned old = atomicInc(&g_ctr, 63u);
        lastflag = (old == 63u);
    }
    __syncthreads();
    if (lastflag) {
        if (tid == 0) {
            float logsum = g_acc[7];
            float n_pos = fmaxf(1.0f, (float)g_np);
            float n_unl = fmaxf(1.0f, (float)(BATCH - g_np));
            float nt = (logsum - g_acc[6]) / (float)NROWS;
            float li, lj;
            {
                float prisk = PRIOR_PRIME / n_pos * g_acc[0];
                float nrisk = (1.0f - PRIOR_PRIME) / (n_unl * (1.0f - PRIOR)) * g_acc[2]
                            - (1.0f - PRIOR_PRIME) * PRIOR / (n_pos * (1.0f - PRIOR)) * g_acc[1];
                li = (nrisk < 0.0f) ? -nrisk : (prisk + nrisk);
            }
            {
                float prisk = PRIOR_PRIME / n_pos * g_acc[3];
                float nrisk = (1.0f - PRIOR_PRIME) / (n_unl * (1.0f - PRIOR)) * g_acc[5]
                            - (1.0f - PRIOR_PRIME) * PRIOR / (n_pos * (1.0f - PRIOR)) * g_acc[4];
                lj = (nrisk < 0.0f) ? -nrisk : (prisk + nrisk);
            }
            float w = w_onnpu[0];
            out[0] = w * 0.5f * (li + lj) + (1.0f - w) * nt;
#pragma unroll
            for (int k = 0; k < 8; ++k) g_acc[k] = 0.0f;
            g_np = 0;
        }
        for (int k = tid; k < NROWS; k += 128) g_S[k] = 0.0f;
    }
}

// ---------------- launch ------------------------------------------------------
extern "C" void kernel_launch(void* const* d_in, const int* in_sizes, int n_in,
                              void* d_out, int out_size) {
    const float* h_i = (const float*)d_in[0];
    const float* h_j = (const float*)d_in[1];
    const float* z_i = (const float*)d_in[2];
    const float* z_j = (const float*)d_in[3];
    const int*   tgt = (const int*)  d_in[4];
    const float* W   = (const float*)d_in[5];
    const float* b   = (const float*)d_in[6];
    const float* wgt = (const float*)d_in[7];
    float* out = (float*)d_out;

    static int smem_set = 0;
    const int SIM_SMEM = 65536 + (128 + 128 + 1) * (int)sizeof(float);  // 66564
    if (!smem_set) {
        cudaFuncSetAttribute(sim_kernel,
                             cudaFuncAttributeMaxDynamicSharedMemorySize, SIM_SMEM);
        smem_set = 1;
    }

    prep_kernel<<<PU_BLOCKS + NORM_BLOCKS, 256>>>(h_i, h_j, z_i, z_j, W, b, tgt);
    sim_kernel<<<NPAIRS, 128, SIM_SMEM>>>();
    final_kernel<<<64, 128>>>(tgt, wgt, out);
}